// round 5
// baseline (speedup 1.0000x reference)
#include <cuda_runtime.h>
#include <cuda_fp16.h>
#include <math_constants.h>

#define HH 512
#define WW 512
#define BB 16
// window p=35, pad=17, chunk=35
// loss = mean(erosion_35x35(min_c x)) - 1   (erosion = separable min filter)

// Intermediate: vertically eroded field, [B, H, W] as half (packed half2 pairs along W)
__device__ __align__(16) __half2 g_t2[BB * HH * WW / 2];
// Per-block partial sums from kernel 2 (512 blocks)
__device__ float g_partial[512];
// Completion counter for fused final reduction (reset each run)
__device__ int g_count;

// ---------------------------------------------------------------------------
// Kernel 1: channel-min of x (fp32 -> fp16) fused with vertical min-filter.
// van Herk chunk 35; suffix+prefix chains INTERLEAVED in one loop (ILP=2).
// Block = (32 lanes, 4 chunks) = 128 thr; tile = 64 W cols x 174 rows (22KB).
// grid = (W/64, B, 4)
// ---------------------------------------------------------------------------
__global__ __launch_bounds__(128) void k1_vert(const float* __restrict__ x) {
    __shared__ __half2 sm[174 * 32];

    const int tx  = threadIdx.x;
    const int ty  = threadIdx.y;
    const int tid = ty * 32 + tx;
    const int wc0 = blockIdx.x * 64;
    const int b   = blockIdx.y;
    const int z   = blockIdx.z;
    const int r0  = z * 140;                 // 4 chunks * 35 rows per z-group
    const float INF = CUDART_INF_F;

    // Load channel-min into smem rows [r0-17, r0+157), as half2 (2 W cols)
    const float* xb = x + (size_t)b * 3 * HH * WW;
    for (int j = tid; j < 174 * 16; j += 128) {
        int r  = j >> 4;
        int c4 = j & 15;                      // float4 slot within 64 cols
        int gh = r0 - 17 + r;
        float4 m;
        if ((unsigned)gh < HH) {
            const float4* p = (const float4*)(xb + (size_t)gh * WW + wc0 + c4 * 4);
            float4 a0 = p[0];
            float4 a1 = p[(HH * WW) / 4];
            float4 a2 = p[(2 * HH * WW) / 4];
            m.x = fminf(a0.x, fminf(a1.x, a2.x));
            m.y = fminf(a0.y, fminf(a1.y, a2.y));
            m.z = fminf(a0.z, fminf(a1.z, a2.z));
            m.w = fminf(a0.w, fminf(a1.w, a2.w));
        } else {
            m = make_float4(INF, INF, INF, INF);
        }
        sm[r * 32 + c4 * 2]     = __floats2half2_rn(m.x, m.y);
        sm[r * 32 + c4 * 2 + 1] = __floats2half2_rn(m.z, m.w);
    }
    __syncthreads();

    const int c    = z * 4 + ty;              // chunk index
    const int base = 35 * c;                  // first output row of chunk
    if (base >= HH) return;
    const int lb = 35 * ty + 17;              // smem row of 'base'
    const __half2 HINF = __float2half2_rn(CUDART_INF_F);

    // Interleaved suffix (rs, backward) + prefix (rp, forward) chains.
    // Both reset at the chunk boundary (k==35).
    __half2 S[35], P[35];
    __half2 rs = HINF, rp = HINF;
    #pragma unroll
    for (int k = 0; k < 52; k++) {
        if (k == 35) { rs = HINF; rp = HINF; }
        rs = __hmin2(rs, sm[(lb + 34 - k) * 32 + tx]);
        rp = __hmin2(rp, sm[(lb + k) * 32 + tx]);
        if (k >= 17) { S[51 - k] = rs; P[k - 17] = rp; }
    }

    // Combine + store: out[base+j] = min(S[j], P[j])
    const size_t ob = (size_t)b * HH;
    const int wcol = (wc0 >> 1) + tx;
    #pragma unroll
    for (int j = 0; j < 35; j++) {
        int i = base + j;
        if (i < HH)
            g_t2[(ob + i) * (WW / 2) + wcol] = __hmin2(S[j], P[j]);
    }
}

// ---------------------------------------------------------------------------
// Kernel 2: horizontal min-filter; half2 packs TWO IMAGE ROWS, smem tile
// transposed [w-slot][row-pair] (pitch 33). Interleaved chains (ILP=2),
// half2 accumulation. Block = (32 row-pair lanes, 4 w-chunks) = 128 thr,
// covers 64 rows x 140 cols. grid = (H/64, B, 4).
// ---------------------------------------------------------------------------
__global__ __launch_bounds__(128) void k2_horiz(float* __restrict__ out) {
    __shared__ __half2 smh2[176 * 33];        // 23.2KB
    __shared__ float red[128];
    __shared__ int isLast;

    const int tx  = threadIdx.x;              // row-pair lane
    const int ty  = threadIdx.y;              // w-chunk within block
    const int tid = ty * 32 + tx;
    const int h0  = blockIdx.x * 64;
    const int b   = blockIdx.y;
    const int z   = blockIdx.z;
    const __half2 HINF2 = __float2half2_rn(CUDART_INF_F);

    // Load tile: w slots [w0-18, w0+158) x 64 rows, transposed into smem.
    {
        const int pbase = 70 * z - 9;         // first half2-pair column index
        #pragma unroll
        for (int i = 0; i < 22; i++) {
            int j  = tid + i * 128;
            int rp = j / 88;                  // row-pair
            int tp = j - rp * 88;             // tile half2-pair slot
            int pc = pbase + tp;              // global half2 column
            __half2 a = HINF2, c = HINF2;
            if ((unsigned)pc < (WW / 2)) {
                size_t o = ((size_t)(b * HH + h0 + 2 * rp)) * (WW / 2) + pc;
                a = g_t2[o];                  // row 2rp   : (w, w+1)
                c = g_t2[o + WW / 2];         // row 2rp+1 : (w, w+1)
            }
            // repack to (row even, row odd) per w column
            smh2[(2 * tp) * 33 + rp]     = __lows2half2(a, c);
            smh2[(2 * tp + 1) * 33 + rp] = __highs2half2(a, c);
        }
    }
    __syncthreads();

    float acc = 0.0f;
    const int chunk = z * 4 + ty;
    const int basew = 35 * chunk;             // first output col of chunk
    if (basew < WW) {
        const int lb = 35 * ty + 18;          // tile slot of 'basew'

        // Interleaved suffix + prefix chains
        __half2 S[35], P[35];
        __half2 rs = HINF2, rp = HINF2;
        #pragma unroll
        for (int k = 0; k < 52; k++) {
            if (k == 35) { rs = HINF2; rp = HINF2; }
            rs = __hmin2(rs, smh2[(lb + 34 - k) * 33 + tx]);
            rp = __hmin2(rp, smh2[(lb + k) * 33 + tx]);
            if (k >= 17) { S[51 - k] = rs; P[k - 17] = rp; }
        }

        // Combine + accumulate in half2 (two interleaved accumulators)
        __half2 a0 = __float2half2_rn(0.0f);
        __half2 a1 = __float2half2_rn(0.0f);
        #pragma unroll
        for (int j = 0; j < 35; j += 2) {
            if (basew + j < WW)     a0 = __hadd2(a0, __hmin2(S[j], P[j]));
            if (j + 1 < 35 && basew + j + 1 < WW)
                                    a1 = __hadd2(a1, __hmin2(S[j + 1], P[j + 1]));
        }
        float2 e = __half22float2(__hadd2(a0, a1));
        acc = e.x + e.y;
    }

    // Deterministic in-block reduction (128 threads)
    red[tid] = acc;
    __syncthreads();
    #pragma unroll
    for (int s = 64; s > 0; s >>= 1) {
        if (tid < s) red[tid] += red[tid + s];
        __syncthreads();
    }
    if (tid == 0) {
        g_partial[b * 32 + z * 8 + blockIdx.x] = red[0];
        __threadfence();
        int done = atomicAdd(&g_count, 1);
        isLast = (done == 511) ? 1 : 0;
    }
    __syncthreads();

    // Last block: deterministic final reduction over the 512 partials
    if (isLast) {
        float v = g_partial[tid] + g_partial[tid + 128] +
                  g_partial[tid + 256] + g_partial[tid + 384];
        red[tid] = v;
        __syncthreads();
        #pragma unroll
        for (int s = 64; s > 0; s >>= 1) {
            if (tid < s) red[tid] += red[tid + s];
            __syncthreads();
        }
        if (tid == 0) {
            out[0] = red[0] * (1.0f / 4194304.0f) - 1.0f;
            g_count = 0;   // reset for next graph replay
        }
    }
}

extern "C" void kernel_launch(void* const* d_in, const int* in_sizes, int n_in,
                              void* d_out, int out_size) {
    const float* x = (const float*)d_in[0];
    float* out = (float*)d_out;

    k1_vert<<<dim3(WW / 64, BB, 4), dim3(32, 4)>>>(x);
    k2_horiz<<<dim3(HH / 64, BB, 4), dim3(32, 4)>>>(out);
}